// round 17
// baseline (speedup 1.0000x reference)
#include <cuda_runtime.h>
#include <cuda_fp16.h>
#include <cstdint>
#include <math.h>

#define CB 32
#define CS 512
#define CE 512
#define CDK 128
#define CH 6
#define CD2 1024
#define CHD 768

// ---------------- sizes (elements) ----------------
constexpr long NB_XP  = (long)CB*CS*CE;
constexpr long NB_QKV = (long)CB*CH*CS*CDK;
constexpr long NB_SC  = (long)CB*CH*CS*CS;
constexpr long NB_Z   = (long)CB*CS*CHD;
constexpr long NB_D2  = (long)CB*CS*CD2;
constexpr long NW_QKV1 = (long)CH*CE*CDK;
constexpr long NW_QKV2 = (long)CH*CD2*CDK;
constexpr long NW_O   = (long)CHD*CD2;
constexpr long NW_F   = (long)CD2*CD2;

// ---------------- fp16 scratch offsets (half elems) ----------------
constexpr long HB_XPH = 0;
constexpr long HB_QH  = HB_XPH + NB_XP;
constexpr long HB_KH  = HB_QH + NB_QKV;
constexpr long HB_VTH = HB_KH + NB_QKV;
constexpr long HB_SCH = HB_VTH + NB_QKV;
constexpr long HB_ATH = HB_SCH + NB_SC;
constexpr long HB_ZH  = HB_ATH + NB_SC;
constexpr long HB_AH  = HB_ZH + NB_Z;
constexpr long HB_FH  = HB_AH + NB_D2;
constexpr long HB_N1H = HB_FH + NB_D2;
constexpr long HB_N2H = HB_N1H + NB_D2;
constexpr long HB_N3H = HB_N2H + NB_D2;
constexpr long HB_W1Q = HB_N3H + NB_D2;
constexpr long HB_W1K = HB_W1Q + NW_QKV1;
constexpr long HB_W1V = HB_W1K + NW_QKV1;
constexpr long HB_W1O = HB_W1V + NW_QKV1;
constexpr long HB_W1F = HB_W1O + NW_O;
constexpr long HB_W2Q = HB_W1F + NW_F;
constexpr long HB_W2K = HB_W2Q + NW_QKV2;
constexpr long HB_W2V = HB_W2K + NW_QKV2;
constexpr long HB_W2O = HB_W2V + NW_QKV2;
constexpr long HB_W2F = HB_W2O + NW_O;
constexpr long HB_END = HB_W2F + NW_F;

constexpr long SCRATCH_TOT = (HB_END + 1) / 2 + 64;
__device__ float g_scratch[SCRATCH_TOT];

// ---------------- helpers ----------------
__device__ __forceinline__ void cp16(uint32_t d, const void* s) {
    asm volatile("cp.async.cg.shared.global [%0], [%1], 16;\n" :: "r"(d), "l"(s));
}

#define MMA16816(c, a, b0, b1)                                              \
    asm volatile("mma.sync.aligned.m16n8k16.row.col.f32.f16.f16.f32 "       \
                 "{%0,%1,%2,%3},{%4,%5,%6,%7},{%8,%9},{%0,%1,%2,%3};"       \
                 : "+f"((c)[0]), "+f"((c)[1]), "+f"((c)[2]), "+f"((c)[3])   \
                 : "r"((a)[0]), "r"((a)[1]), "r"((a)[2]), "r"((a)[3]),      \
                   "r"(b0), "r"(b1))

// ---------------- positional encoding + add (fused) ----------------
__global__ void addpos_hi(const float* __restrict__ X,
                          __half* __restrict__ xh, long n) {
    long idx = (long)blockIdx.x * blockDim.x + threadIdx.x;
    if (idx >= n) return;
    int r = (int)(idx & (long)(CS * CE - 1));
    int e = r & 511;
    int s = r >> 9;
    int m = e >> 1;
    float ang = (m >= 128) ? (float)s * 1e-4f : (float)s;
    float pe = (e & 1) ? cosf(ang) : sinf(ang);
    xh[idx] = __float2half(X[idx] + pe);
}

// ---------------- batched transpose f32->hi (up to 3 tensors) ----------
__global__ void transpose_hi3(const float* __restrict__ i0,
                              const float* __restrict__ i1,
                              const float* __restrict__ i2,
                              __half* __restrict__ o0,
                              __half* __restrict__ o1,
                              __half* __restrict__ o2,
                              int R, int C, int zper) {
    __shared__ float t[32][33];
    int zz = blockIdx.z;
    int sel = zz / zper;
    int z = zz - sel * zper;
    const float* in = (sel == 0) ? i0 : (sel == 1) ? i1 : i2;
    __half* oh = (sel == 0) ? o0 : (sel == 1) ? o1 : o2;
    long zo = (long)z * R * C;
    int c0 = blockIdx.x * 32, r0 = blockIdx.y * 32;
    int tx = threadIdx.x, ty = threadIdx.y;
    #pragma unroll
    for (int i = 0; i < 32; i += 8)
        t[ty + i][tx] = in[zo + (long)(r0 + ty + i) * C + c0 + tx];
    __syncthreads();
    #pragma unroll
    for (int i = 0; i < 32; i += 8) {
        float v = t[tx][ty + i];
        long o = zo + (long)(c0 + ty + i) * R + r0 + tx;
        oh[o] = __float2half(v);
    }
}

// ================== GEMM core, BK=64, 3-stage pipeline =================
// Stage: A 128x64 half @0 (pitch 144B), B 128x64 half @18432.
#define STGB 36864
#define GSMEM (3 * STGB)   // 110592

__device__ __forceinline__ void g_load(
    uint32_t sbase, int stage,
    const __half* ga_h, const __half* gb_h, int k0, int tid)
{
    uint32_t d = sbase + stage * STGB + tid * 144;
    #pragma unroll
    for (int c = 0; c < 8; ++c) {
        cp16(d + c * 16,         ga_h + k0 + c * 8);
        cp16(d + 18432 + c * 16, gb_h + k0 + c * 8);
    }
    asm volatile("cp.async.commit_group;");
}

template<bool TANH>
__device__ __forceinline__ void gemm_body(
    uint8_t* smem, const __half* ga_h, const __half* gb_h,
    const float* bias, __half* Chp,
    int K, int ldc, int m0, int n0, float alpha,
    int tid, int wid, int lane, bool transC)
{
    int g = lane >> 2, tig = lane & 3;
    int wm = (wid & 1) * 64, wn = (wid >> 1) * 64;
    uint32_t sbase = (uint32_t)__cvta_generic_to_shared(smem);

    float acc[4][8][4];
    #pragma unroll
    for (int i = 0; i < 4; ++i)
        #pragma unroll
        for (int j = 0; j < 8; ++j)
            #pragma unroll
            for (int q = 0; q < 4; ++q) acc[i][j][q] = 0.f;

    int nk = K / 64;
    g_load(sbase, 0, ga_h, gb_h, 0, tid);
    if (nk > 1) g_load(sbase, 1, ga_h, gb_h, 64, tid);

    for (int kc = 0; kc < nk; ++kc) {
        if (kc + 2 < nk) {
            g_load(sbase, (kc + 2) % 3, ga_h, gb_h, (kc + 2) * 64, tid);
            asm volatile("cp.async.wait_group 2;");
        } else if (kc + 1 < nk) {
            asm volatile("cp.async.wait_group 1;");
        } else {
            asm volatile("cp.async.wait_group 0;");
        }
        __syncthreads();

        const uint8_t* sb_ = smem + (kc % 3) * STGB;
        #pragma unroll
        for (int ks = 0; ks < 4; ++ks) {
            int cb = ks * 32 + tig * 4;
            uint32_t ah[4][4];
            #pragma unroll
            for (int mt = 0; mt < 4; ++mt) {
                const uint8_t* p = sb_ + (wm + mt * 16 + g) * 144 + cb;
                ah[mt][0] = *(const uint32_t*)(p);
                ah[mt][1] = *(const uint32_t*)(p + 8 * 144);
                ah[mt][2] = *(const uint32_t*)(p + 16);
                ah[mt][3] = *(const uint32_t*)(p + 8 * 144 + 16);
            }
            #pragma unroll
            for (int nt = 0; nt < 8; ++nt) {
                const uint8_t* pb = sb_ + 18432 + (wn + nt * 8 + g) * 144 + cb;
                uint32_t bh0 = *(const uint32_t*)(pb);
                uint32_t bh1 = *(const uint32_t*)(pb + 16);
                #pragma unroll
                for (int mt = 0; mt < 4; ++mt)
                    MMA16816(acc[mt][nt], ah[mt], bh0, bh1);
            }
        }
        __syncthreads();
    }

    if (!transC) {
        #pragma unroll
        for (int nt = 0; nt < 8; ++nt) {
            int col = n0 + wn + nt * 8 + tig * 2;
            float bb0 = 0.f, bb1 = 0.f;
            if (bias) { bb0 = bias[col - n0]; bb1 = bias[col - n0 + 1]; }
            #pragma unroll
            for (int mt = 0; mt < 4; ++mt) {
                int r0 = m0 + wm + mt * 16 + g;
                float v00 = acc[mt][nt][0] * alpha + bb0;
                float v01 = acc[mt][nt][1] * alpha + bb1;
                float v10 = acc[mt][nt][2] * alpha + bb0;
                float v11 = acc[mt][nt][3] * alpha + bb1;
                if (TANH) { v00 = tanhf(v00); v01 = tanhf(v01); v10 = tanhf(v10); v11 = tanhf(v11); }
                __half2 hh;
                hh.x = __float2half(v00); hh.y = __float2half(v01);
                *(__half2*)(Chp + (long)r0 * ldc + col) = hh;
                hh.x = __float2half(v10); hh.y = __float2half(v11);
                *(__half2*)(Chp + (long)(r0 + 8) * ldc + col) = hh;
            }
        }
    } else {
        __half* st = (__half*)smem;
        #pragma unroll
        for (int nt = 0; nt < 8; ++nt) {
            int col = wn + nt * 8 + tig * 2;
            float bb0 = bias[col], bb1 = bias[col + 1];
            #pragma unroll
            for (int mt = 0; mt < 4; ++mt) {
                int r0 = wm + mt * 16 + g;
                st[(long)col * 130 + r0]           = __float2half(acc[mt][nt][0] + bb0);
                st[(long)(col + 1) * 130 + r0]     = __float2half(acc[mt][nt][1] + bb1);
                st[(long)col * 130 + r0 + 8]       = __float2half(acc[mt][nt][2] + bb0);
                st[(long)(col + 1) * 130 + r0 + 8] = __float2half(acc[mt][nt][3] + bb1);
            }
        }
        __syncthreads();
        int dk0 = tid >> 6;
        int t2 = (tid & 63) * 2;
        #pragma unroll
        for (int d0 = 0; d0 < 128; d0 += 2) {
            int dk = d0 + dk0;
            __half2 v;
            v.x = st[(long)dk * 130 + t2];
            v.y = st[(long)dk * 130 + t2 + 1];
            *(__half2*)(Chp + (long)dk * ldc + m0 + t2) = v;
        }
    }
}

// ---------------- generic GEMM (fp16 out) ----------------
template<bool TANH>
__global__ void __launch_bounds__(128, 2) gemm3(
    const __half* __restrict__ Ah,
    const __half* __restrict__ Bh,
    const float* __restrict__ biasb,
    __half* __restrict__ Ch,
    int K, int lda, int ldb, int ldc, int Hdiv,
    long sA_b, long sA_h, long sB_b, long sB_h,
    long sC_b, long sC_h, long sBias_h, float alpha)
{
    extern __shared__ uint8_t smem[];
    int z = blockIdx.z, zb = z / Hdiv, zh_ = z - zb * Hdiv;
    int m0 = blockIdx.y * 128, n0 = blockIdx.x * 128;
    int tid = threadIdx.x, wid = tid >> 5, lane = tid & 31;
    const __half* ga = Ah + zb * sA_b + zh_ * sA_h + (long)(m0 + tid) * lda;
    const __half* gb = Bh + zb * sB_b + zh_ * sB_h + (long)(n0 + tid) * ldb;
    __half* Chp = Ch + zb * sC_b + zh_ * sC_h;
    const float* bias = biasb ? biasb + (long)zh_ * sBias_h + n0 : nullptr;
    gemm_body<TANH>(smem, ga, gb, bias, Chp, K, ldc, m0, n0, alpha, tid, wid, lane, false);
}

// ---------------- merged QKV GEMM (V written transposed) ---------------
__global__ void __launch_bounds__(128, 2) gemm_qkv(
    const __half* __restrict__ Ah,
    const __half* __restrict__ Bq, const __half* __restrict__ Bk,
    const __half* __restrict__ Bv,
    const float* __restrict__ bq, const float* __restrict__ bk,
    const float* __restrict__ bv,
    __half* __restrict__ Cq, __half* __restrict__ Ck, __half* __restrict__ Cvt,
    int K)
{
    extern __shared__ uint8_t smem[];
    int sel = blockIdx.x;
    int z = blockIdx.z, zb = z / CH, zh_ = z - zb * CH;
    int m0 = blockIdx.y * 128;
    int tid = threadIdx.x, wid = tid >> 5, lane = tid & 31;

    const __half* Bh = (sel == 0) ? Bq : (sel == 1) ? Bk : Bv;
    const float* bb  = (sel == 0) ? bq : (sel == 1) ? bk : bv;

    long sA_b = (long)CS * K;
    long sB_h = (long)CDK * K;

    const __half* ga = Ah + zb * sA_b + (long)(m0 + tid) * K;
    const __half* gb = Bh + zh_ * sB_h + (long)tid * K;
    const float* bias = bb + (long)zh_ * CDK;

    if (sel < 2) {
        __half* Ch = (sel == 0) ? Cq : Ck;
        __half* Chp = Ch + zb * (long)CH * CS * CDK + zh_ * (long)CS * CDK;
        gemm_body<false>(smem, ga, gb, bias, Chp, K, CDK, m0, 0, 1.f, tid, wid, lane, false);
    } else {
        __half* Chp = Cvt + zb * (long)CH * CDK * CS + zh_ * (long)CDK * CS;
        gemm_body<false>(smem, ga, gb, bias, Chp, K, CS, m0, 0, 1.f, tid, wid, lane, true);
    }
}

// ---------------- softmax over the QUERY axis (packed regs) -----------
__global__ void __launch_bounds__(512) softmax_q2(const __half* __restrict__ Sc,
                                                  __half* __restrict__ oh) {
    __shared__ float2 sm[16][32], sl[16][32];
    long base = (long)blockIdx.x * CS * CS + blockIdx.y * 64;
    int w = threadIdx.x >> 5, lane = threadIdx.x & 31;
    const __half* p = Sc + base + (long)w * 32 * CS + lane * 2;
    __half2 v2[32];
    __half2 hm = __float2half2_rn(-60000.f);
    #pragma unroll
    for (int i = 0; i < 32; ++i) {
        v2[i] = *(const __half2*)(p + (long)i * CS);
        hm = __hmax2(hm, v2[i]);
    }
    float m0 = __half2float(__low2half(hm));
    float m1 = __half2float(__high2half(hm));
    float l0 = 0.f, l1 = 0.f;
    #pragma unroll
    for (int i = 0; i < 32; ++i) {
        float e0 = __expf(__half2float(__low2half(v2[i])) - m0);
        float e1 = __expf(__half2float(__high2half(v2[i])) - m1);
        l0 += e0; l1 += e1;
        v2[i] = __floats2half2_rn(e0, e1);
    }
    sm[w][lane] = make_float2(m0, m1);
    sl[w][lane] = make_float2(l0, l1);
    __syncthreads();
    float M0 = -1e30f, M1 = -1e30f;
    #pragma unroll
    for (int ww = 0; ww < 16; ++ww) {
        M0 = fmaxf(M0, sm[ww][lane].x);
        M1 = fmaxf(M1, sm[ww][lane].y);
    }
    float L0 = 0.f, L1 = 0.f;
    #pragma unroll
    for (int ww = 0; ww < 16; ++ww) {
        L0 += sl[ww][lane].x * __expf(sm[ww][lane].x - M0);
        L1 += sl[ww][lane].y * __expf(sm[ww][lane].y - M1);
    }
    __half2 sc2 = __floats2half2_rn(__expf(m0 - M0) / L0, __expf(m1 - M1) / L1);
    __half* po = oh + base + (long)w * 32 * CS + lane * 2;
    #pragma unroll
    for (int i = 0; i < 32; ++i)
        *(__half2*)(po + (long)i * CS) = __hmul2(v2[i], sc2);
}

// ---------------- batch-norm, fp16-out variant (packed regs) -----------
__global__ void bn16_h(const __half* __restrict__ x,
                       const __half* __restrict__ add, int addw,
                       __half* __restrict__ oh) {
    int j2 = blockIdx.x * blockDim.x + threadIdx.x;
    if (j2 >= CS * CD2 / 2) return;
    int j = j2 * 2;
    const long SD = (long)CS * CD2;
    int s = j >> 10;
    int e = j & 1023;
    int ae = e & (addw - 1);
    long aoff = (long)s * addw + ae;

    __half2 t2[CB];
    float sum0 = 0.f, sum1 = 0.f, sq0 = 0.f, sq1 = 0.f;
    #pragma unroll
    for (int b = 0; b < CB; ++b) {
        __half2 xa = *(const __half2*)(x + (long)b * SD + j);
        __half2 ad = *(const __half2*)(add + (long)b * CS * addw + aoff);
        float t0 = __half2float(__low2half(xa)) + __half2float(__low2half(ad));
        float t1 = __half2float(__high2half(xa)) + __half2float(__high2half(ad));
        t2[b] = __floats2half2_rn(t0, t1);
        sum0 += t0; sum1 += t1;
        sq0 += t0 * t0; sq1 += t1 * t1;
    }
    float mean0 = sum0 * (1.f / CB), mean1 = sum1 * (1.f / CB);
    float var0 = sq0 * (1.f / CB) - mean0 * mean0;
    float var1 = sq1 * (1.f / CB) - mean1 * mean1;
    float rstd0 = rsqrtf(var0 + 1e-3f);
    float rstd1 = rsqrtf(var1 + 1e-3f);
    #pragma unroll
    for (int b = 0; b < CB; ++b) {
        float o0 = (__half2float(__low2half(t2[b])) - mean0) * rstd0;
        float o1 = (__half2float(__high2half(t2[b])) - mean1) * rstd1;
        *(__half2*)(oh + (long)b * SD + j) = __floats2half2_rn(o0, o1);
    }
}

// ---------------- batch-norm, f32-out variant (final) ------------------
__global__ void bn16_f(const __half* __restrict__ x,
                       const __half* __restrict__ add, int addw,
                       float* __restrict__ outf) {
    int j2 = blockIdx.x * blockDim.x + threadIdx.x;
    if (j2 >= CS * CD2 / 2) return;
    int j = j2 * 2;
    const long SD = (long)CS * CD2;
    int s = j >> 10;
    int e = j & 1023;
    int ae = e & (addw - 1);
    long aoff = (long)s * addw + ae;

    float v0[CB], v1[CB];
    float sum0 = 0.f, sum1 = 0.f;
    #pragma unroll
    for (int b = 0; b < CB; ++b) {
        __half2 xa = *(const __half2*)(x + (long)b * SD + j);
        __half2 ad = *(const __half2*)(add + (long)b * CS * addw + aoff);
        float t0 = __half2float(__low2half(xa)) + __half2float(__low2half(ad));
        float t1 = __half2float(__high2half(xa)) + __half2float(__high2half(ad));
        v0[b] = t0; v1[b] = t1;
        sum0 += t0; sum1 += t1;
    }
    float mean0 = sum0 * (1.f / CB), mean1 = sum1 * (1.f / CB);
    float var0 = 0.f, var1 = 0.f;
    #pragma unroll
    for (int b = 0; b < CB; ++b) {
        float d0 = v0[b] - mean0, d1 = v1[b] - mean1;
        var0 += d0 * d0; var1 += d1 * d1;
    }
    float rstd0 = rsqrtf(var0 * (1.f / CB) + 1e-3f);
    float rstd1 = rsqrtf(var1 * (1.f / CB) + 1e-3f);
    #pragma unroll
    for (int b = 0; b < CB; ++b) {
        float o0 = (v0[b] - mean0) * rstd0;
        float o1 = (v1[b] - mean1) * rstd1;
        *(float2*)(outf + (long)b * SD + j) = make_float2(o0, o1);
    }
}

// ---------------- host orchestration ----------------
struct Ptrs {
    __half* hb;
};

static void run_attn(int Din, const __half* xh,
                     const __half* WqT, const __half* WkT, const __half* WvT,
                     const float* bq, const float* bk, const float* bv,
                     const __half* WoT, const float* bo, Ptrs p, __half* aout)
{
    __half *qh = p.hb + HB_QH;
    __half *kh = p.hb + HB_KH;
    __half *vth = p.hb + HB_VTH;
    __half *sch = p.hb + HB_SCH;
    __half *ath = p.hb + HB_ATH;
    __half *zh = p.hb + HB_ZH;

    gemm_qkv<<<dim3(3, CS / 128, CB * CH), 128, GSMEM>>>(
        xh, WqT, WkT, WvT, bq, bk, bv, qh, kh, vth, Din);

    // scores = Q @ K^T * 1/sqrt(dk), fp32 accumulators
    gemm3<false><<<dim3(CS / 128, CS / 128, CB * CH), 128, GSMEM>>>(
        qh, kh, nullptr, sch,
        CDK, CDK, CDK, CS, 1,
        (long)CS * CDK, 0, (long)CS * CDK, 0, (long)CS * CS, 0, 0,
        0.08838834764831845f);

    softmax_q2<<<dim3(CB * CH, CS / 64), 512>>>(sch, ath);

    gemm3<false><<<dim3(1, CS / 128, CB * CH), 128, GSMEM>>>(
        ath, vth, nullptr, zh,
        CS, CS, CS, CHD, CH,
        (long)CH * CS * CS, (long)CS * CS,
        (long)CH * CDK * CS, (long)CDK * CS,
        (long)CS * CHD, CDK, 0, 1.f);

    gemm3<false><<<dim3(CD2 / 128, (CB * CS) / 128, 1), 128, GSMEM>>>(
        zh, WoT, bo, aout,
        CHD, CHD, CHD, CD2, 1, 0, 0, 0, 0, 0, 0, 0, 1.f);
}

extern "C" void kernel_launch(void* const* d_in, const int* in_sizes, int n_in,
                              void* d_out, int out_size)
{
    const float* X    = (const float*)d_in[0];
    const float* Wq1  = (const float*)d_in[1];
    const float* Wk1  = (const float*)d_in[2];
    const float* Wv1  = (const float*)d_in[3];
    const float* bq1  = (const float*)d_in[4];
    const float* bk1  = (const float*)d_in[5];
    const float* bv1  = (const float*)d_in[6];
    const float* Wo1  = (const float*)d_in[7];
    const float* bo1  = (const float*)d_in[8];
    const float* Wff1 = (const float*)d_in[9];
    const float* bff1 = (const float*)d_in[10];
    const float* Wq2  = (const float*)d_in[11];
    const float* Wk2  = (const float*)d_in[12];
    const float* Wv2  = (const float*)d_in[13];
    const float* bq2  = (const float*)d_in[14];
    const float* bk2  = (const float*)d_in[15];
    const float* bv2  = (const float*)d_in[16];
    const float* Wo2  = (const float*)d_in[17];
    const float* bo2  = (const float*)d_in[18];
    const float* Wff2 = (const float*)d_in[19];
    const float* bff2 = (const float*)d_in[20];
    float* out = (float*)d_out;

    float* sb = nullptr;
    cudaGetSymbolAddress((void**)&sb, g_scratch);
    Ptrs p;
    p.hb = (__half*)sb;

    cudaFuncSetAttribute(gemm3<false>, cudaFuncAttributeMaxDynamicSharedMemorySize, GSMEM);
    cudaFuncSetAttribute(gemm3<true>,  cudaFuncAttributeMaxDynamicSharedMemorySize, GSMEM);
    cudaFuncSetAttribute(gemm_qkv,     cudaFuncAttributeMaxDynamicSharedMemorySize, GSMEM);

    // ----- batched weight transposes (4 launches) -----
    dim3 tb(32, 8);
    transpose_hi3<<<dim3(CDK/32, CE/32, 3*CH), tb>>>(
        Wq1, Wk1, Wv1, p.hb+HB_W1Q, p.hb+HB_W1K, p.hb+HB_W1V, CE, CDK, CH);
    transpose_hi3<<<dim3(CDK/32, CD2/32, 3*CH), tb>>>(
        Wq2, Wk2, Wv2, p.hb+HB_W2Q, p.hb+HB_W2K, p.hb+HB_W2V, CD2, CDK, CH);
    transpose_hi3<<<dim3(CD2/32, CHD/32, 2), tb>>>(
        Wo1, Wo2, Wo1, p.hb+HB_W1O, p.hb+HB_W2O, p.hb+HB_W1O, CHD, CD2, 1);
    transpose_hi3<<<dim3(CD2/32, CD2/32, 2), tb>>>(
        Wff1, Wff2, Wff1, p.hb+HB_W1F, p.hb+HB_W2F, p.hb+HB_W1F, CD2, CD2, 1);

    addpos_hi<<<(unsigned)((NB_XP + 255) / 256), 256>>>(X, p.hb + HB_XPH, NB_XP);

    __half* ah  = p.hb + HB_AH;
    __half* fh  = p.hb + HB_FH;
    __half* n1h = p.hb + HB_N1H;
    __half* n2h = p.hb + HB_N2H;
    __half* n3h = p.hb + HB_N3H;
    int nbn = (CS * CD2 / 2 + 255) / 256;
    dim3 gff(CD2 / 128, (CB * CS) / 128, 1);

    // ----- block 1: attention (Din = 512) -----
    run_attn(CE, p.hb + HB_XPH,
             p.hb+HB_W1Q, p.hb+HB_W1K, p.hb+HB_W1V, bq1, bk1, bv1,
             p.hb+HB_W1O, bo1, p, ah);
    bn16_h<<<nbn, 256>>>(ah, p.hb + HB_XPH, CE, n1h);

    // ----- block 2: FFN -----
    gemm3<true><<<gff, 128, GSMEM>>>(
        n1h, p.hb + HB_W1F, bff1, fh,
        CD2, CD2, CD2, CD2, 1, 0, 0, 0, 0, 0, 0, 0, 1.f);
    bn16_h<<<nbn, 256>>>(fh, n1h, CD2, n2h);

    // ----- block 3: attention (Din = 1024) -----
    run_attn(CD2, n2h,
             p.hb+HB_W2Q, p.hb+HB_W2K, p.hb+HB_W2V, bq2, bk2, bv2,
             p.hb+HB_W2O, bo2, p, ah);
    bn16_h<<<nbn, 256>>>(ah, n2h, CD2, n3h);

    // ----- block 4: FFN -----
    gemm3<true><<<gff, 128, GSMEM>>>(
        n3h, p.hb + HB_W2F, bff2, fh,
        CD2, CD2, CD2, CD2, 1, 0, 0, 0, 0, 0, 0, 0, 1.f);
    bn16_f<<<nbn, 256>>>(fh, n3h, CD2, out);
}